// round 1
// baseline (speedup 1.0000x reference)
#include <cuda_runtime.h>
#include <stdint.h>

#define IN_SIZE  4096
#define OUT_SIZE 4096
#define BATCH    256

// Dense scatter target for the COO weight. 64 MB device global (allowed scratch).
__device__ float g_W[(size_t)IN_SIZE * OUT_SIZE];
__device__ int   g_idx_is64;

// ---------------------------------------------------------------------------
// Zero W. Grid sized exactly: IN*OUT/4 float4 elements.
// ---------------------------------------------------------------------------
__global__ void zero_w_kernel() {
    size_t i = (size_t)blockIdx.x * blockDim.x + threadIdx.x;
    float4 z = make_float4(0.f, 0.f, 0.f, 0.f);
    reinterpret_cast<float4*>(g_W)[i] = z;
}

// ---------------------------------------------------------------------------
// Detect idx dtype (int64 vs int32). Values are in [0, 4096), so in an int64
// little-endian layout every odd u32 word (hi half) is zero. In int32 layout
// odd words are random column indices — 64 consecutive zeros is impossible
// in practice (P ≈ 4096^-64).
// ---------------------------------------------------------------------------
__global__ void detect_idx_kernel(const uint32_t* __restrict__ idx_words) {
    if (threadIdx.x == 0) {
        uint32_t acc = 0;
#pragma unroll
        for (int i = 0; i < 64; ++i) acc |= idx_words[2 * i + 1];
        g_idx_is64 = (acc == 0u) ? 1 : 0;
    }
}

// ---------------------------------------------------------------------------
// Scatter: g_W[row, col] += val. Duplicates must accumulate -> atomicAdd.
// W lives entirely in L2, so these are L2-resident REDG-class atomics.
// ---------------------------------------------------------------------------
__global__ void scatter_kernel(const void* __restrict__ idx,
                               const float* __restrict__ val,
                               int nnz) {
    int i = blockIdx.x * blockDim.x + threadIdx.x;
    if (i >= nnz) return;
    int row, col;
    if (g_idx_is64) {
        longlong2 p = reinterpret_cast<const longlong2*>(idx)[i];
        row = (int)p.x;
        col = (int)p.y;
    } else {
        int2 p = reinterpret_cast<const int2*>(idx)[i];
        row = p.x;
        col = p.y;
    }
    atomicAdd(&g_W[(size_t)row * OUT_SIZE + col], val[i]);
}

// ---------------------------------------------------------------------------
// Tiled fp32 SGEMM: out[256,4096] = relu(X[256,4096] @ g_W[4096,4096] + bias).
// BM=128, BN=64, BK=16, 256 threads, 8x4 micro-tile per thread.
// Grid = (4096/64, 256/128) = (64, 2) = 128 CTAs  ->  one wave on 148 SMs.
// ---------------------------------------------------------------------------
#define BM 128
#define BN 64
#define BK 16

__global__ __launch_bounds__(256, 1)
void gemm_bias_relu_kernel(const float* __restrict__ X,
                           const float* __restrict__ bias,
                           float* __restrict__ out) {
    __shared__ float As[BK][BM];   // A tile, transposed: As[k][m]
    __shared__ float Bs[BK][BN];   // B tile: Bs[k][n]

    const int tid = threadIdx.x;
    const int tx  = tid & 15;      // 0..15 -> 4 cols each
    const int ty  = tid >> 4;      // 0..15 -> 8 rows each

    const int n0 = blockIdx.x * BN;
    const int m0 = blockIdx.y * BM;

    float acc[8][4];
#pragma unroll
    for (int i = 0; i < 8; ++i)
#pragma unroll
        for (int j = 0; j < 4; ++j) acc[i][j] = 0.f;

    // A-load mapping: 128 rows x 4 float4 per row = 512 float4 / 256 thr = 2 each
    const int a_row0 = tid >> 2;          // 0..63  (iter 0), +64 (iter 1)
    const int a_kv   = tid & 3;           // which float4 in the 16-wide k slab
    // B-load mapping: 16 rows x 16 float4 per row = 256 float4, 1 each
    const int b_kr = tid >> 4;            // 0..15
    const int b_nv = tid & 15;            // 0..15

    for (int k0 = 0; k0 < IN_SIZE; k0 += BK) {
        // load A (X tile) transposed into As
#pragma unroll
        for (int t = 0; t < 2; ++t) {
            int row = a_row0 + t * 64;
            float4 v = *reinterpret_cast<const float4*>(
                &X[(size_t)(m0 + row) * IN_SIZE + k0 + a_kv * 4]);
            As[a_kv * 4 + 0][row] = v.x;
            As[a_kv * 4 + 1][row] = v.y;
            As[a_kv * 4 + 2][row] = v.z;
            As[a_kv * 4 + 3][row] = v.w;
        }
        // load B (W tile)
        {
            float4 v = *reinterpret_cast<const float4*>(
                &g_W[(size_t)(k0 + b_kr) * OUT_SIZE + n0 + b_nv * 4]);
            *reinterpret_cast<float4*>(&Bs[b_kr][b_nv * 4]) = v;
        }
        __syncthreads();

#pragma unroll
        for (int k = 0; k < BK; ++k) {
            float a[8], b[4];
            float4 a0 = *reinterpret_cast<const float4*>(&As[k][ty * 8 + 0]);
            float4 a1 = *reinterpret_cast<const float4*>(&As[k][ty * 8 + 4]);
            a[0] = a0.x; a[1] = a0.y; a[2] = a0.z; a[3] = a0.w;
            a[4] = a1.x; a[5] = a1.y; a[6] = a1.z; a[7] = a1.w;
            float4 bv = *reinterpret_cast<const float4*>(&Bs[k][tx * 4]);
            b[0] = bv.x; b[1] = bv.y; b[2] = bv.z; b[3] = bv.w;
#pragma unroll
            for (int i = 0; i < 8; ++i)
#pragma unroll
                for (int j = 0; j < 4; ++j)
                    acc[i][j] = fmaf(a[i], b[j], acc[i][j]);
        }
        __syncthreads();
    }

    // epilogue: bias + relu, float4 stores
    const int col = n0 + tx * 4;
    float4 bv = *reinterpret_cast<const float4*>(&bias[col]);
#pragma unroll
    for (int i = 0; i < 8; ++i) {
        int row = m0 + ty * 8 + i;
        float4 r;
        r.x = fmaxf(acc[i][0] + bv.x, 0.f);
        r.y = fmaxf(acc[i][1] + bv.y, 0.f);
        r.z = fmaxf(acc[i][2] + bv.z, 0.f);
        r.w = fmaxf(acc[i][3] + bv.w, 0.f);
        *reinterpret_cast<float4*>(&out[(size_t)row * OUT_SIZE + col]) = r;
    }
}

// ---------------------------------------------------------------------------
// kernel_launch — graph-capturable: kernel launches only, no allocs, no syncs.
// Input order (metadata): X [256*4096 f32], idx [NNZ*2 int], val [NNZ f32],
// bias [4096 f32]. Output: [256*4096] f32.
// ---------------------------------------------------------------------------
extern "C" void kernel_launch(void* const* d_in, const int* in_sizes, int n_in,
                              void* d_out, int out_size) {
    const float* X    = (const float*)d_in[0];
    const void*  idx  = d_in[1];
    const float* val  = (const float*)d_in[2];
    const float* bias = (const float*)d_in[3];
    float*       out  = (float*)d_out;

    const int nnz = in_sizes[2];  // element count of val == NNZ

    // 1) zero W: 4096*4096/4 float4 = 4,194,304 -> 16384 blocks x 256
    zero_w_kernel<<<(int)(((size_t)IN_SIZE * OUT_SIZE / 4) / 256), 256>>>();

    // 2) detect idx dtype
    detect_idx_kernel<<<1, 32>>>((const uint32_t*)idx);

    // 3) scatter COO values into dense W (atomic accumulate for duplicates)
    scatter_kernel<<<(nnz + 255) / 256, 256>>>(idx, val, nnz);

    // 4) GEMM + bias + relu
    dim3 grid(OUT_SIZE / BN, BATCH / BM);
    gemm_bias_relu_kernel<<<grid, 256>>>(X, bias, out);
}

// round 3
// speedup vs baseline: 1.8500x; 1.8500x over previous
#include <cuda_runtime.h>
#include <stdint.h>

#define IN_SIZE  4096
#define OUT_SIZE 4096
#define BATCH    256

#define BK      32
#define NSTAGE  (IN_SIZE / BK)     // 128

// Transposed dense weight: g_Wt[out][in] (K-major rows for the GEMM B operand)
__device__ float g_Wt[(size_t)IN_SIZE * OUT_SIZE];
__device__ int   g_idx_is64;

// ---------------------------------------------------------------------------
// helpers
// ---------------------------------------------------------------------------
__device__ __forceinline__ uint32_t f2tf32(float f) {
    uint32_t u;
    asm("cvt.rna.tf32.f32 %0, %1;" : "=r"(u) : "f"(f));
    return u;
}

__device__ __forceinline__ void mma_tf32(float& d0, float& d1, float& d2, float& d3,
                                         uint32_t a0, uint32_t a1, uint32_t a2, uint32_t a3,
                                         uint32_t b0, uint32_t b1) {
    asm volatile(
        "mma.sync.aligned.m16n8k8.row.col.f32.tf32.tf32.f32 "
        "{%0,%1,%2,%3}, {%4,%5,%6,%7}, {%8,%9}, {%0,%1,%2,%3};"
        : "+f"(d0), "+f"(d1), "+f"(d2), "+f"(d3)
        : "r"(a0), "r"(a1), "r"(a2), "r"(a3), "r"(b0), "r"(b1));
}

// ---------------------------------------------------------------------------
// Zero Wt (64 MB, float4 stores)
// ---------------------------------------------------------------------------
__global__ void zero_w_kernel() {
    size_t i = (size_t)blockIdx.x * blockDim.x + threadIdx.x;
    reinterpret_cast<float4*>(g_Wt)[i] = make_float4(0.f, 0.f, 0.f, 0.f);
}

// ---------------------------------------------------------------------------
// Detect idx dtype: indices < 4096, so int64 layout has all odd u32 words zero.
// ---------------------------------------------------------------------------
__global__ void detect_idx_kernel(const uint32_t* __restrict__ idx_words) {
    if (threadIdx.x == 0) {
        uint32_t acc = 0;
#pragma unroll
        for (int i = 0; i < 64; ++i) acc |= idx_words[2 * i + 1];
        g_idx_is64 = (acc == 0u) ? 1 : 0;
    }
}

// ---------------------------------------------------------------------------
// Scatter: g_Wt[col][row] += val (duplicates accumulate)
// ---------------------------------------------------------------------------
__global__ void scatter_kernel(const void* __restrict__ idx,
                               const float* __restrict__ val,
                               int nnz) {
    int i = blockIdx.x * blockDim.x + threadIdx.x;
    if (i >= nnz) return;
    int row, col;
    if (g_idx_is64) {
        longlong2 p = reinterpret_cast<const longlong2*>(idx)[i];
        row = (int)p.x;
        col = (int)p.y;
    } else {
        int2 p = reinterpret_cast<const int2*>(idx)[i];
        row = p.x;
        col = p.y;
    }
    atomicAdd(&g_Wt[(size_t)col * IN_SIZE + row], val[i]);
}

// ---------------------------------------------------------------------------
// tf32 mma.sync GEMM: out[256,4096] = relu(X @ W + bias), W = g_Wt^T.
//
// CTA 128x128, 8 warps as 2(m) x 4(n), warp tile 64x32.
// K staged 32 per iteration, double-buffered (2 x 32 KB).
//
// SMEM is stored in a fragment-permuted layout so that each mma fragment reg
// is a single conflict-free 32-bit LDS:
//   A_perm[ksub(4)][msub(8)][vi(4)][pos(32)]   (16 KB / stage)
//   B_perm[ksub(4)][nsub(16)][vi(2)][pos(32)]  (16 KB / stage)
// where for element (m, k): ksub=k>>3, msub=m>>4, r=m&15, c=k&7,
//   lane = (r&7)*4 + (c&3), vi = (r>>3) | ((c>>2)<<1)       (A)
//   lane = (n&7)*4 + (c&3), vi = (c>>2)                     (B)
// and pos = lane ^ (g<<2), g = ksub*2 + (c>>2)  (XOR swizzle; keeps both the
// STS.128 staging writes and the per-fragment LDS.32 reads conflict-free).
// ---------------------------------------------------------------------------
#define SMEM_BYTES (2 * 32768)

__global__ __launch_bounds__(256, 1)
void gemm_tf32_mma(const float* __restrict__ X,
                   const float* __restrict__ bias,
                   float* __restrict__ out) {
    extern __shared__ uint32_t smu[];   // 2 stages x (A 16KB | B 16KB)

    const int tid   = threadIdx.x;
    const int lane  = tid & 31;
    const int wid   = tid >> 5;
    const int warpm = wid & 1;          // 0..1
    const int warpn = wid >> 1;         // 0..3
    const int m0 = blockIdx.y * 128;
    const int n0 = blockIdx.x * 128;

    // ---- staging: thread (srow, sj) loads float4 (row srow+32i, k sj*4..+3)
    const int srow = tid >> 3;          // 0..31
    const int sj   = tid & 7;           // float4 index within 32-wide k stage
    const float* Ag = X    + (size_t)(m0 + srow) * IN_SIZE + sj * 4;
    const float* Bg = g_Wt + (size_t)(n0 + srow) * IN_SIZE + sj * 4;

    // permuted STS offsets (bytes within stage region) for rows srow + 32*i
    uint32_t offA[4], offB[4];
#pragma unroll
    for (int i = 0; i < 4; ++i) {
        int m = srow + 32 * i;
        uint32_t posx = (uint32_t)((((m & 7) * 4) ^ (sj << 2)) << 2);   // g = sj
        offA[i] = (uint32_t)((sj >> 1) * 4096 + (m >> 4) * 512 +
                             ((((m & 15) >> 3) | ((sj & 1) << 1)) * 128)) + posx;
        offB[i] = (uint32_t)((sj >> 1) * 4096 + (m >> 3) * 256 +
                             ((sj & 1) * 128)) + posx;
    }

    float acc[4][4][4];                 // [msub][nsub][di]
#pragma unroll
    for (int a = 0; a < 4; ++a)
#pragma unroll
        for (int b = 0; b < 4; ++b)
#pragma unroll
            for (int d = 0; d < 4; ++d) acc[a][b][d] = 0.f;

    // ---- prologue: stage 0
    float4 ra[4], rb[4];
#pragma unroll
    for (int i = 0; i < 4; ++i) {
        ra[i] = *reinterpret_cast<const float4*>(Ag + (size_t)(32 * i) * IN_SIZE);
        rb[i] = *reinterpret_cast<const float4*>(Bg + (size_t)(32 * i) * IN_SIZE);
    }
#pragma unroll
    for (int i = 0; i < 4; ++i) {
        uint4 va = make_uint4(f2tf32(ra[i].x), f2tf32(ra[i].y), f2tf32(ra[i].z), f2tf32(ra[i].w));
        uint4 vb = make_uint4(f2tf32(rb[i].x), f2tf32(rb[i].y), f2tf32(rb[i].z), f2tf32(rb[i].w));
        *reinterpret_cast<uint4*>((char*)smu + offA[i])         = va;
        *reinterpret_cast<uint4*>((char*)smu + 16384 + offB[i]) = vb;
    }
    __syncthreads();

    const uint32_t abase = (uint32_t)(warpm * 4) * 512;   // msubg offset
    const uint32_t bbase = (uint32_t)(warpn * 4) * 256;   // nsubg offset

    for (int s = 0; s < NSTAGE; ++s) {
        const uint32_t cur = (uint32_t)(s & 1) * 32768;

        // prefetch next stage into registers (overlaps with compute)
        if (s + 1 < NSTAGE) {
            const float* ga = Ag + (s + 1) * BK;
            const float* gb = Bg + (s + 1) * BK;
#pragma unroll
            for (int i = 0; i < 4; ++i) {
                ra[i] = *reinterpret_cast<const float4*>(ga + (size_t)(32 * i) * IN_SIZE);
                rb[i] = *reinterpret_cast<const float4*>(gb + (size_t)(32 * i) * IN_SIZE);
            }
        }

        // compute current stage: 4 k8-steps
        const uint32_t* As = (const uint32_t*)((char*)smu + cur);
        const uint32_t* Bs = (const uint32_t*)((char*)smu + cur + 16384);
#pragma unroll
        for (int ks = 0; ks < 4; ++ks) {
            uint32_t afrag[4][4];
#pragma unroll
            for (int msub = 0; msub < 4; ++msub)
#pragma unroll
                for (int vi = 0; vi < 4; ++vi) {
                    const int g = ks * 2 + (vi >> 1);
                    const uint32_t word =
                        (uint32_t)(ks * 1024) + (abase >> 2) + (uint32_t)(msub * 128) +
                        (uint32_t)(vi * 32) + (uint32_t)(lane ^ (g << 2));
                    afrag[msub][vi] = As[word];
                }
            uint32_t bfrag[4][2];
#pragma unroll
            for (int nsub = 0; nsub < 4; ++nsub)
#pragma unroll
                for (int vi = 0; vi < 2; ++vi) {
                    const int g = ks * 2 + vi;
                    const uint32_t word =
                        (uint32_t)(ks * 1024) + (bbase >> 2) + (uint32_t)(nsub * 64) +
                        (uint32_t)(vi * 32) + (uint32_t)(lane ^ (g << 2));
                    bfrag[nsub][vi] = Bs[word];
                }
#pragma unroll
            for (int msub = 0; msub < 4; ++msub)
#pragma unroll
                for (int nsub = 0; nsub < 4; ++nsub)
                    mma_tf32(acc[msub][nsub][0], acc[msub][nsub][1],
                             acc[msub][nsub][2], acc[msub][nsub][3],
                             afrag[msub][0], afrag[msub][1],
                             afrag[msub][2], afrag[msub][3],
                             bfrag[nsub][0], bfrag[nsub][1]);
        }

        // stage next buffer
        if (s + 1 < NSTAGE) {
            const uint32_t nxt = (uint32_t)((s + 1) & 1) * 32768;
#pragma unroll
            for (int i = 0; i < 4; ++i) {
                uint4 va = make_uint4(f2tf32(ra[i].x), f2tf32(ra[i].y), f2tf32(ra[i].z), f2tf32(ra[i].w));
                uint4 vb = make_uint4(f2tf32(rb[i].x), f2tf32(rb[i].y), f2tf32(rb[i].z), f2tf32(rb[i].w));
                *reinterpret_cast<uint4*>((char*)smu + nxt + offA[i])         = va;
                *reinterpret_cast<uint4*>((char*)smu + nxt + 16384 + offB[i]) = vb;
            }
        }
        __syncthreads();
    }

    // ---- epilogue: bias + relu, float2 stores
#pragma unroll
    for (int msub = 0; msub < 4; ++msub) {
        const int m = m0 + warpm * 64 + msub * 16 + (lane >> 2);
#pragma unroll
        for (int nsub = 0; nsub < 4; ++nsub) {
            const int n = n0 + warpn * 32 + nsub * 8 + (lane & 3) * 2;
            float2 bv = *reinterpret_cast<const float2*>(bias + n);
            float2 o0, o1;
            o0.x = fmaxf(acc[msub][nsub][0] + bv.x, 0.f);
            o0.y = fmaxf(acc[msub][nsub][1] + bv.y, 0.f);
            o1.x = fmaxf(acc[msub][nsub][2] + bv.x, 0.f);
            o1.y = fmaxf(acc[msub][nsub][3] + bv.y, 0.f);
            *reinterpret_cast<float2*>(out + (size_t)m * OUT_SIZE + n)       = o0;
            *reinterpret_cast<float2*>(out + (size_t)(m + 8) * OUT_SIZE + n) = o1;
        }
    }
}

// ---------------------------------------------------------------------------
// kernel_launch
// ---------------------------------------------------------------------------
extern "C" void kernel_launch(void* const* d_in, const int* in_sizes, int n_in,
                              void* d_out, int out_size) {
    const float* X    = (const float*)d_in[0];
    const void*  idx  = d_in[1];
    const float* val  = (const float*)d_in[2];
    const float* bias = (const float*)d_in[3];
    float*       out  = (float*)d_out;

    const int nnz = in_sizes[2];

    zero_w_kernel<<<(int)(((size_t)IN_SIZE * OUT_SIZE / 4) / 256), 256>>>();
    detect_idx_kernel<<<1, 32>>>((const uint32_t*)idx);
    scatter_kernel<<<(nnz + 255) / 256, 256>>>(idx, val, nnz);

    cudaFuncSetAttribute(gemm_tf32_mma,
                         cudaFuncAttributeMaxDynamicSharedMemorySize, SMEM_BYTES);
    dim3 grid(OUT_SIZE / 128, BATCH / 128);   // (32, 2) = 64 CTAs
    gemm_tf32_mma<<<grid, 256, SMEM_BYTES>>>(X, bias, out);
}